// round 10
// baseline (speedup 1.0000x reference)
#include <cuda_runtime.h>
#include <cuda_bf16.h>
#include <stdint.h>
#include <math.h>

// B,H,F,T = 1024,1024,64,48
#define BB 1024
#define HH 1024
#define FF 64
#define TT 48

#define BM 128
#define BN 128
#define NTH 256
#define KT_TOTAL 34   // 32 h-tiles + 2 act-tiles

// smem stage layout (bytes): A hi/lo 8K each, B hi/lo 8K each
#define OFF_AHI 0
#define OFF_ALO 8192
#define OFF_BHI 16384
#define OFF_BLO 24576
#define STAGE_BYTES 32768
#define NSTAGES 3
#define SMEM_TOTAL (NSTAGES * STAGE_BYTES)

// ---------------- persistent device state ----------------
__device__ __nv_bfloat16 g_hhi[2][BB * HH];
__device__ __nv_bfloat16 g_hlo[2][BB * HH];
__device__ float         g_c[BB * HH];
__device__ __nv_bfloat16 g_Bhi[4096 * 1024];   // permuted rkernel, row n' = 4j+q, len 1024
__device__ __nv_bfloat16 g_Blo[4096 * 1024];
__device__ __nv_bfloat16 g_Khi[4096 * 64];     // permuted kernel, row n' = 4j+q, len 64
__device__ __nv_bfloat16 g_Klo[4096 * 64];
// per-row mu/sigma partial dot products: [row][nblk*4 + wn]
__device__ float g_p1[BB * 128];
__device__ float g_p2[BB * 128];
// t=0 mu/sigma (from context_state)
__device__ float g_mu[BB];
__device__ float g_sg[BB];

// ---------------- helpers ----------------
__device__ __forceinline__ uint32_t smem_u32(const void* p) {
    uint32_t a;
    asm("{ .reg .u64 t; cvta.to.shared.u64 t, %1; cvt.u32.u64 %0, t; }" : "=r"(a) : "l"(p));
    return a;
}
__device__ __forceinline__ void cpa16(uint32_t dst, const void* src) {
    asm volatile("cp.async.cg.shared.global [%0], [%1], 16;" :: "r"(dst), "l"(src));
}
__device__ __forceinline__ void cp_commit() {
    asm volatile("cp.async.commit_group;" ::: "memory");
}
__device__ __forceinline__ void cp_wait1() {
    asm volatile("cp.async.wait_group 1;" ::: "memory");
}
__device__ __forceinline__ void ldsm4(uint32_t r[4], uint32_t addr) {
    asm volatile("ldmatrix.sync.aligned.m8n8.x4.shared.b16 {%0,%1,%2,%3}, [%4];"
                 : "=r"(r[0]), "=r"(r[1]), "=r"(r[2]), "=r"(r[3]) : "r"(addr));
}
__device__ __forceinline__ void mma_bf16(float c[4], const uint32_t a[4], const uint32_t b[2]) {
    asm volatile(
        "mma.sync.aligned.m16n8k16.row.col.f32.bf16.bf16.f32 "
        "{%0,%1,%2,%3}, {%4,%5,%6,%7}, {%8,%9}, {%0,%1,%2,%3};"
        : "+f"(c[0]), "+f"(c[1]), "+f"(c[2]), "+f"(c[3])
        : "r"(a[0]), "r"(a[1]), "r"(a[2]), "r"(a[3]), "r"(b[0]), "r"(b[1]));
}
__device__ __forceinline__ float sigf(float x) {
    return __fdividef(1.0f, 1.0f + __expf(-x));
}
__device__ __forceinline__ float tanh_acc(float x) {
    return 2.0f * sigf(2.0f * x) - 1.0f;
}
// act value -> bf16 hi/lo fragment halves
__device__ __forceinline__ void make_act_frag(float mu, float sg, float2 e,
                                              uint32_t& hi, uint32_t& lo) {
    float a0 = fminf(fmaxf(fmaf(sg, e.x, mu), 0.0f), 1.0f);
    float a1 = fminf(fmaxf(fmaf(sg, e.y, mu), 0.0f), 1.0f);
    __nv_bfloat16 h0 = __float2bfloat16_rn(a0);
    __nv_bfloat16 h1 = __float2bfloat16_rn(a1);
    __nv_bfloat162 hp = __halves2bfloat162(h0, h1);
    hi = *reinterpret_cast<uint32_t*>(&hp);
    __nv_bfloat162 lp = __halves2bfloat162(
        __float2bfloat16_rn(a0 - __bfloat162float(h0)),
        __float2bfloat16_rn(a1 - __bfloat162float(h1)));
    lo = *reinterpret_cast<uint32_t*>(&lp);
}

// rkern (1024 x 4096) -> Bhi/Blo rows n' = 4j+q, k-major
__global__ __launch_bounds__(256) void convert_rkern_kernel(const float* __restrict__ rk) {
    __shared__ float tile[32][33];
    int n0 = blockIdx.x * 32, k0 = blockIdx.y * 32;
    int tid = threadIdx.x;
    for (int e = tid; e < 1024; e += 256) {
        int kr = e >> 5, nc = e & 31;
        tile[kr][nc] = rk[(size_t)(k0 + kr) * 4096 + n0 + nc];
    }
    __syncthreads();
    int nl = tid >> 3, ks = tid & 7;
    int n = n0 + nl;
    int q = n >> 10, j = n & 1023;
    int np = j * 4 + q;
    #pragma unroll
    for (int i = 0; i < 4; ++i) {
        int k = k0 + ks * 4 + i;
        float x = tile[ks * 4 + i][nl];
        __nv_bfloat16 hi = __float2bfloat16_rn(x);
        g_Bhi[(size_t)np * 1024 + k] = hi;
        g_Blo[(size_t)np * 1024 + k] = __float2bfloat16_rn(x - __bfloat162float(hi));
    }
}

// kern (64 x 4096) -> Khi/Klo rows n' = 4j+q, k-major (len 64)
__global__ __launch_bounds__(256) void convert_kern_kernel(const float* __restrict__ kn) {
    __shared__ float tile[32][33];
    int n0 = blockIdx.x * 32, k0 = blockIdx.y * 32;
    int tid = threadIdx.x;
    for (int e = tid; e < 1024; e += 256) {
        int kr = e >> 5, nc = e & 31;
        tile[kr][nc] = kn[(size_t)(k0 + kr) * 4096 + n0 + nc];
    }
    __syncthreads();
    int nl = tid >> 3, ks = tid & 7;
    int n = n0 + nl;
    int q = n >> 10, j = n & 1023;
    int np = j * 4 + q;
    #pragma unroll
    for (int i = 0; i < 4; ++i) {
        int k = k0 + ks * 4 + i;
        float x = tile[ks * 4 + i][nl];
        __nv_bfloat16 hi = __float2bfloat16_rn(x);
        g_Khi[(size_t)np * 64 + k] = hi;
        g_Klo[(size_t)np * 64 + k] = __float2bfloat16_rn(x - __bfloat162float(hi));
    }
}

// ---------------- t=0 kernel: mu/sigma from context_state; zero-init h/c ----------------
__global__ __launch_bounds__(256) void act0_kernel(
    const float* __restrict__ cs,
    const float* __restrict__ w1, const float* __restrict__ b1,
    const float* __restrict__ w2, const float* __restrict__ b2,
    float* __restrict__ out)
{
    const int tid = threadIdx.x;
    const int wrow = tid >> 5;
    const int lane = tid & 31;
    const int row = blockIdx.x * 8 + wrow;
    const int k0 = lane * 32;

    // zero-init this block's 8 rows of h (buffer 0) and c
    {
        size_t base = (size_t)blockIdx.x * 8 * HH;
        for (int i = tid; i < 8 * HH / 2; i += 256) {
            ((uint32_t*)&g_hhi[0][base])[i] = 0u;
            ((uint32_t*)&g_hlo[0][base])[i] = 0u;
            ((float2*)&g_c[base])[i] = make_float2(0.0f, 0.0f);
        }
    }

    float s1 = 0.0f, s2 = 0.0f;
    const float* srow = cs + (size_t)row * (3 * HH) + 2 * HH + k0;
    #pragma unroll
    for (int i = 0; i < 8; ++i) {
        float4 v = *(const float4*)(srow + i * 4);
        const float* wp1 = w1 + k0 + i * 4;
        const float* wp2 = w2 + k0 + i * 4;
        s1 = fmaf(v.x, wp1[0], s1); s2 = fmaf(v.x, wp2[0], s2);
        s1 = fmaf(v.y, wp1[1], s1); s2 = fmaf(v.y, wp2[1], s2);
        s1 = fmaf(v.z, wp1[2], s1); s2 = fmaf(v.z, wp2[2], s2);
        s1 = fmaf(v.w, wp1[3], s1); s2 = fmaf(v.w, wp2[3], s2);
    }
    #pragma unroll
    for (int off = 16; off > 0; off >>= 1) {
        s1 += __shfl_xor_sync(0xffffffffu, s1, off);
        s2 += __shfl_xor_sync(0xffffffffu, s2, off);
    }
    if (lane == 0) {
        float mu = fmaxf(s1 + b1[0], 0.0f);
        float xr = fmaxf(s2 + b2[0], 0.0f);
        float sg = xr + log1pf(expf(-xr)) + 1e-8f;
        g_mu[row] = mu;
        g_sg[row] = sg;
        out[row] = mu;                       // mus t=0
        out[(size_t)TT * BB + row] = sg;     // sigmas t=0
    }
}

// ---------------- cp.async tile loader ----------------
__device__ __forceinline__ void issue_tile_loads(
    uint32_t sA, int tid, int mrow0, int ncol0,
    const __nv_bfloat16* ah, const __nv_bfloat16* al,
    const __nv_bfloat16* bh, const __nv_bfloat16* bl,
    int bstride, int koff, bool loadA)
{
    const int lrow = tid >> 2, lch = tid & 3;
    if (loadA) {
        #pragma unroll
        for (int rr = 0; rr < 2; ++rr) {
            int m = lrow + rr * 64;
            uint32_t d = sA + (uint32_t)(m * 64 + ((lch ^ ((m >> 1) & 3)) << 4));
            size_t gsrc = (size_t)(mrow0 + m) * 1024 + koff + lch * 8;
            cpa16(d + OFF_AHI, ah + gsrc);
            cpa16(d + OFF_ALO, al + gsrc);
        }
    }
    #pragma unroll
    for (int rr = 0; rr < 2; ++rr) {
        int n = lrow + rr * 64;
        uint32_t d = sA + (uint32_t)(n * 64 + ((lch ^ ((n >> 1) & 3)) << 4));
        size_t gsrc = (size_t)(ncol0 + n) * bstride + koff + lch * 8;
        cpa16(d + OFF_BHI, bh + gsrc);
        cpa16(d + OFF_BLO, bl + gsrc);
    }
}

// ---------------- main fused GEMM + act + gate kernel ----------------
__global__ __launch_bounds__(NTH, 2) void gemm_step_kernel(
    const float* __restrict__ bias,
    const float* __restrict__ w1, const float* __restrict__ w2,
    const float* __restrict__ b1, const float* __restrict__ b2,
    const float* __restrict__ eps_t,
    float* __restrict__ out, int t, int hb)
{
    extern __shared__ char smem[];
    __shared__ float sbias[4][32];
    __shared__ float w1s[32], w2s[32];
    __shared__ float mu_s[128], sg_s[128];
    const int tid = threadIdx.x;
    const int nblk = blockIdx.x;         // 0..31
    const int mblk = blockIdx.y;         // 0..7
    const int mrow0 = mblk * BM;
    const int ncol0 = nblk * BN;         // permuted n' space
    const uint32_t sbase = smem_u32(smem);

    const int lane = tid & 31;
    const int w = tid >> 5;
    const int wm = w >> 2;   // 0..1  (64 rows each)
    const int wn = w & 3;    // 0..3  (32 n' each)

    const __nv_bfloat16* hh_src = g_hhi[hb];
    const __nv_bfloat16* hl_src = g_hlo[hb];

    // ---- pipeline prologue: get loads in flight first ----
    issue_tile_loads(sbase, tid, mrow0, ncol0, hh_src, hl_src, g_Bhi, g_Blo, 1024, 0, true);
    cp_commit();
    issue_tile_loads(sbase + STAGE_BYTES, tid, mrow0, ncol0, hh_src, hl_src, g_Bhi, g_Blo, 1024, 32, true);
    cp_commit();

    // ---- small smem loads ----
    if (tid < 128) {
        sbias[tid >> 5][tid & 31] = bias[(size_t)(tid >> 5) * 1024 + nblk * 32 + (tid & 31)];
    } else if (tid < 160) {
        w1s[tid - 128] = w1[nblk * 32 + (tid - 128)];
    } else if (tid < 192) {
        w2s[tid - 160] = w2[nblk * 32 + (tid - 160)];
    }

    // ---- mu/sigma for this CTA's 128 rows (redundant across nblk) ----
    if (t == 0) {
        if (tid < 128) mu_s[tid] = g_mu[mrow0 + tid];
        else if (tid < 256) sg_s[tid - 128] = g_sg[mrow0 + tid - 128];
    } else {
        if (tid < 128) {
            const float4* p = (const float4*)&g_p1[(size_t)(mrow0 + tid) * 128];
            float a0 = 0, a1 = 0, a2 = 0, a3 = 0;
            #pragma unroll
            for (int i = 0; i < 8; ++i) {
                float4 v0 = p[i * 4 + 0], v1 = p[i * 4 + 1];
                float4 v2 = p[i * 4 + 2], v3 = p[i * 4 + 3];
                a0 += (v0.x + v0.y) + (v0.z + v0.w);
                a1 += (v1.x + v1.y) + (v1.z + v1.w);
                a2 += (v2.x + v2.y) + (v2.z + v2.w);
                a3 += (v3.x + v3.y) + (v3.z + v3.w);
            }
            mu_s[tid] = (a0 + a1) + (a2 + a3);
        } else {
            const float4* p = (const float4*)&g_p2[(size_t)(mrow0 + tid - 128) * 128];
            float a0 = 0, a1 = 0, a2 = 0, a3 = 0;
            #pragma unroll
            for (int i = 0; i < 8; ++i) {
                float4 v0 = p[i * 4 + 0], v1 = p[i * 4 + 1];
                float4 v2 = p[i * 4 + 2], v3 = p[i * 4 + 3];
                a0 += (v0.x + v0.y) + (v0.z + v0.w);
                a1 += (v1.x + v1.y) + (v1.z + v1.w);
                a2 += (v2.x + v2.y) + (v2.z + v2.w);
                a3 += (v3.x + v3.y) + (v3.z + v3.w);
            }
            sg_s[tid - 128] = (a0 + a1) + (a2 + a3);
        }
    }
    __syncthreads();
    if (t != 0 && tid < 128) {
        float mu = fmaxf(mu_s[tid] + b1[0], 0.0f);
        float xr = fmaxf(sg_s[tid] + b2[0], 0.0f);
        float sg = xr + log1pf(expf(-xr)) + 1e-8f;
        mu_s[tid] = mu;
        sg_s[tid] = sg;
        if (nblk == 0) {
            out[(size_t)t * BB + mrow0 + tid] = mu;
            out[(size_t)TT * BB + (size_t)t * BB + mrow0 + tid] = sg;
        }
    }
    __syncthreads();

    // acts output (nblk==0 only)
    if (nblk == 0) {
        #pragma unroll 4
        for (int it = 0; it < 32; ++it) {
            int idx = tid + it * 256;
            int r = idx >> 6, f = idx & 63;
            float a = fminf(fmaxf(fmaf(sg_s[r], eps_t[(size_t)(mrow0 + r) * 64 + f], mu_s[r]), 0.0f), 1.0f);
            out[2 * (size_t)TT * BB + ((size_t)(mrow0 + r) * TT + t) * 64 + f] = a;
        }
    }

    // ---- fragment address precompute ----
    const int mat = lane >> 3;
    const int r8 = lane & 7;
    int a_off[4], a_sw[4];
    #pragma unroll
    for (int mt = 0; mt < 4; ++mt) {
        int m = wm * 64 + mt * 16 + r8 + (mat & 1) * 8;
        a_off[mt] = m * 64;
        a_sw[mt] = (m >> 1) & 3;
    }
    const int a_cbit = mat >> 1;
    int b_off[2], b_sw[2];
    #pragma unroll
    for (int np = 0; np < 2; ++np) {
        int n = wn * 32 + np * 16 + r8 + (mat >> 1) * 8;
        b_off[np] = n * 64;
        b_sw[np] = (n >> 1) & 3;
    }
    const int b_cbit = mat & 1;

    float acc[4][4][4];
    #pragma unroll
    for (int mt = 0; mt < 4; ++mt)
        #pragma unroll
        for (int nt = 0; nt < 4; ++nt)
            #pragma unroll
            for (int e = 0; e < 4; ++e)
                acc[mt][nt][e] = 0.0f;

    // ---- main loop ----
    for (int kt = 0; kt < KT_TOTAL; ++kt) {
        cp_wait1();
        __syncthreads();
        if (kt == 30) {
            // warm L2 for eps (used by act fragments at kt 32/33)
            const float* ep = eps_t + (size_t)(mrow0 + (tid >> 1)) * 64 + (tid & 1) * 32;
            asm volatile("prefetch.global.L2 [%0];" :: "l"(ep));
        }
        int kn = kt + 2;
        if (kn < KT_TOTAL) {
            uint32_t sN = sbase + (kn % NSTAGES) * STAGE_BYTES;
            if (kn < 32)
                issue_tile_loads(sN, tid, mrow0, ncol0, hh_src, hl_src,
                                 g_Bhi, g_Blo, 1024, kn * 32, true);
            else
                issue_tile_loads(sN, tid, mrow0, ncol0, nullptr, nullptr,
                                 g_Khi, g_Klo, 64, (kn - 32) * 32, false);
        }
        cp_commit();

        const uint32_t sA = sbase + (kt % NSTAGES) * STAGE_BYTES;
        if (kt < 32) {
            #pragma unroll
            for (int s = 0; s < 2; ++s) {
                uint32_t ahi[4][4], bhi[2][4], alo[4][4], blo[2][4];
                #pragma unroll
                for (int mt = 0; mt < 4; ++mt)
                    ldsm4(ahi[mt], sA + OFF_AHI + a_off[mt] + (((2 * s + a_cbit) ^ a_sw[mt]) << 4));
                #pragma unroll
                for (int np = 0; np < 2; ++np)
                    ldsm4(bhi[np], sA + OFF_BHI + b_off[np] + (((2 * s + b_cbit) ^ b_sw[np]) << 4));
                #pragma unroll
                for (int mt = 0; mt < 4; ++mt)
                    ldsm4(alo[mt], sA + OFF_ALO + a_off[mt] + (((2 * s + a_cbit) ^ a_sw[mt]) << 4));
                // pass 1: hi*hi (hides alo latency)
                #pragma unroll
                for (int mt = 0; mt < 4; ++mt)
                    #pragma unroll
                    for (int nt = 0; nt < 4; ++nt)
                        mma_bf16(acc[mt][nt], ahi[mt], &bhi[nt >> 1][(nt & 1) * 2]);
                #pragma unroll
                for (int np = 0; np < 2; ++np)
                    ldsm4(blo[np], sA + OFF_BLO + b_off[np] + (((2 * s + b_cbit) ^ b_sw[np]) << 4));
                // pass 2: lo*hi (hides blo latency)
                #pragma unroll
                for (int mt = 0; mt < 4; ++mt)
                    #pragma unroll
                    for (int nt = 0; nt < 4; ++nt)
                        mma_bf16(acc[mt][nt], alo[mt], &bhi[nt >> 1][(nt & 1) * 2]);
                // pass 3: hi*lo
                #pragma unroll
                for (int mt = 0; mt < 4; ++mt)
                    #pragma unroll
                    for (int nt = 0; nt < 4; ++nt)
                        mma_bf16(acc[mt][nt], ahi[mt], &blo[nt >> 1][(nt & 1) * 2]);
            }
        } else {
            // act k-chunks: build A fragments arithmetically (no smem A)
            const int fb = (kt - 32) * 32;
            #pragma unroll
            for (int s = 0; s < 2; ++s) {
                const int fs = fb + s * 16 + 2 * (lane & 3);
                uint32_t ahi[4][4], alo[4][4], bhi[2][4], blo[2][4];
                #pragma unroll
                for (int mt = 0; mt < 4; ++mt) {
                    int r0l = wm * 64 + mt * 16 + (lane >> 2);
                    int r1l = r0l + 8;
                    float m0 = mu_s[r0l], s0 = sg_s[r0l];
                    float m1 = mu_s[r1l], s1v = sg_s[r1l];
                    const float* e0 = eps_t + (size_t)(mrow0 + r0l) * 64 + fs;
                    const float* e1 = eps_t + (size_t)(mrow0 + r1l) * 64 + fs;
                    float2 ea = *(const float2*)e0;
                    float2 eb = *(const float2*)e1;
                    float2 ec = *(const float2*)(e0 + 8);
                    float2 ed = *(const float2*)(e1 + 8);
                    make_act_frag(m0, s0, ea, ahi[mt][0], alo[mt][0]);
                    make_act_frag(m1, s1v, eb, ahi[mt][1], alo[mt][1]);
                    make_act_frag(m0, s0, ec, ahi[mt][2], alo[mt][2]);
                    make_act_frag(m1, s1v, ed, ahi[mt][3], alo[mt][3]);
                }
                #pragma unroll
                for (int np = 0; np < 2; ++np) {
                    ldsm4(bhi[np], sA + OFF_BHI + b_off[np] + (((2 * s + b_cbit) ^ b_sw[np]) << 4));
                    ldsm4(blo[np], sA + OFF_BLO + b_off[np] + (((2 * s + b_cbit) ^ b_sw[np]) << 4));
                }
                #pragma unroll
                for (int mt = 0; mt < 4; ++mt)
                    #pragma unroll
                    for (int nt = 0; nt < 4; ++nt)
                        mma_bf16(acc[mt][nt], ahi[mt], &bhi[nt >> 1][(nt & 1) * 2]);
                #pragma unroll
                for (int mt = 0; mt < 4; ++mt)
                    #pragma unroll
                    for (int nt = 0; nt < 4; ++nt)
                        mma_bf16(acc[mt][nt], alo[mt], &bhi[nt >> 1][(nt & 1) * 2]);
                #pragma unroll
                for (int mt = 0; mt < 4; ++mt)
                    #pragma unroll
                    for (int nt = 0; nt < 4; ++nt)
                        mma_bf16(acc[mt][nt], ahi[mt], &blo[nt >> 1][(nt & 1) * 2]);
            }
        }
    }

    // ---- epilogue: gate exchange via shfl, LSTM update, mu/sigma partials ----
    const int odd = lane & 1;
    #pragma unroll
    for (int mt = 0; mt < 4; ++mt) {
        const int r = mrow0 + wm * 64 + mt * 16 + (lane >> 2) + odd * 8;
        float p1 = 0.0f, p2 = 0.0f;
        #pragma unroll
        for (int nt = 0; nt < 4; ++nt) {
            float* c = acc[mt][nt];
            float q0 = __shfl_xor_sync(0xffffffffu, c[0], 1);
            float q1 = __shfl_xor_sync(0xffffffffu, c[1], 1);
            float q2 = __shfl_xor_sync(0xffffffffu, c[2], 1);
            float q3 = __shfl_xor_sync(0xffffffffu, c[3], 1);
            float zi = odd ? q2 : c[0];
            float zf = odd ? q3 : c[1];
            float zg = odd ? c[2] : q0;
            float zo = odd ? c[3] : q1;
            int jl = wn * 8 + nt * 2 + ((lane & 3) >> 1);
            float vi = zi + sbias[0][jl];
            float vf = zf + sbias[1][jl];
            float vg = zg + sbias[2][jl];
            float vo = zo + sbias[3][jl];
            size_t idx = (size_t)r * 1024 + nblk * 32 + jl;
            float co = g_c[idx];
            float cn = sigf(vf) * co + sigf(vi) * tanh_acc(vg);
            float hn = sigf(vo) * tanh_acc(cn);
            g_c[idx] = cn;
            __nv_bfloat16 hh = __float2bfloat16_rn(hn);
            g_hhi[hb ^ 1][idx] = hh;
            g_hlo[hb ^ 1][idx] = __float2bfloat16_rn(hn - __bfloat162float(hh));
            p1 = fmaf(hn, w1s[jl], p1);
            p2 = fmaf(hn, w2s[jl], p2);
        }
        p1 += __shfl_xor_sync(0xffffffffu, p1, 2);
        p2 += __shfl_xor_sync(0xffffffffu, p2, 2);
        if ((lane & 2) == 0) {
            size_t slot = (size_t)r * 128 + nblk * 4 + wn;
            g_p1[slot] = p1;
            g_p2[slot] = p2;
        }
    }
}

// ---------------- host ----------------
extern "C" void kernel_launch(void* const* d_in, const int* in_sizes, int n_in,
                              void* d_out, int out_size) {
    const float* cs    = (const float*)d_in[0];
    const float* w1    = (const float*)d_in[1];
    const float* b1    = (const float*)d_in[2];
    const float* w2    = (const float*)d_in[3];
    const float* b2    = (const float*)d_in[4];
    const float* kern  = (const float*)d_in[5];
    const float* rkern = (const float*)d_in[6];
    const float* bias  = (const float*)d_in[7];
    const float* eps   = (const float*)d_in[8];
    float* out = (float*)d_out;

    cudaFuncSetAttribute(gemm_step_kernel,
                         cudaFuncAttributeMaxDynamicSharedMemorySize, SMEM_TOTAL);

    // launch order: conv, conv, act0, gemm -> gemm lands in ncu slot 5
    convert_rkern_kernel<<<dim3(4096 / 32, 1024 / 32), 256>>>(rkern);
    convert_kern_kernel<<<dim3(4096 / 32, 64 / 32), 256>>>(kern);
    act0_kernel<<<128, 256>>>(cs, w1, b1, w2, b2, out);

    dim3 g2(32, 8);  // nblk x mblk = 256 CTAs
    for (int t = 0; t < TT; ++t) {
        gemm_step_kernel<<<g2, NTH, SMEM_TOTAL>>>(
            bias, w1, w2, b1, b2, eps + (size_t)t * BB * FF, out, t, t & 1);
    }
}

// round 12
// speedup vs baseline: 1.2477x; 1.2477x over previous
#include <cuda_runtime.h>
#include <cuda_bf16.h>
#include <stdint.h>
#include <math.h>

// B,H,F,T = 1024,1024,64,48
#define BB 1024
#define HH 1024
#define FF 64
#define TT 48

#define BM 128
#define BN 128
#define NTH 256
#define KT_TOTAL 34   // 32 h-tiles + 2 act-tiles

// smem stage layout (bytes): A hi/lo 8K each, B hi/lo 8K each
#define OFF_AHI 0
#define OFF_ALO 8192
#define OFF_BHI 16384
#define OFF_BLO 24576
#define STAGE_BYTES 32768
#define NSTAGES 3
#define SMEM_TOTAL (NSTAGES * STAGE_BYTES)

// ---------------- persistent device state ----------------
__device__ __nv_bfloat16 g_hhi[2][BB * HH];
__device__ __nv_bfloat16 g_hlo[2][BB * HH];
__device__ float         g_c[BB * HH];
__device__ __nv_bfloat16 g_Bhi[4096 * 1024];   // permuted rkernel, row n' = 4j+q, len 1024
__device__ __nv_bfloat16 g_Blo[4096 * 1024];
__device__ __nv_bfloat16 g_Khi[4096 * 64];     // permuted kernel, row n' = 4j+q, len 64
__device__ __nv_bfloat16 g_Klo[4096 * 64];
// per-(row,nblk) mu/sigma partials, double-buffered by step parity
__device__ float g_p1[2][BB * 32];
__device__ float g_p2[2][BB * 32];
// t=0 mu/sigma (from context_state)
__device__ float g_mu[BB];
__device__ float g_sg[BB];

// ---------------- helpers ----------------
__device__ __forceinline__ uint32_t smem_u32(const void* p) {
    uint32_t a;
    asm("{ .reg .u64 t; cvta.to.shared.u64 t, %1; cvt.u32.u64 %0, t; }" : "=r"(a) : "l"(p));
    return a;
}
__device__ __forceinline__ void cpa16(uint32_t dst, const void* src) {
    asm volatile("cp.async.cg.shared.global [%0], [%1], 16;" :: "r"(dst), "l"(src));
}
__device__ __forceinline__ void cp_commit() {
    asm volatile("cp.async.commit_group;" ::: "memory");
}
__device__ __forceinline__ void cp_wait1() {
    asm volatile("cp.async.wait_group 1;" ::: "memory");
}
__device__ __forceinline__ void ldsm4(uint32_t r[4], uint32_t addr) {
    asm volatile("ldmatrix.sync.aligned.m8n8.x4.shared.b16 {%0,%1,%2,%3}, [%4];"
                 : "=r"(r[0]), "=r"(r[1]), "=r"(r[2]), "=r"(r[3]) : "r"(addr));
}
__device__ __forceinline__ void mma_bf16(float c[4], const uint32_t a[4], const uint32_t b[2]) {
    asm volatile(
        "mma.sync.aligned.m16n8k16.row.col.f32.bf16.bf16.f32 "
        "{%0,%1,%2,%3}, {%4,%5,%6,%7}, {%8,%9}, {%0,%1,%2,%3};"
        : "+f"(c[0]), "+f"(c[1]), "+f"(c[2]), "+f"(c[3])
        : "r"(a[0]), "r"(a[1]), "r"(a[2]), "r"(a[3]), "r"(b[0]), "r"(b[1]));
}
__device__ __forceinline__ float sigf(float x) {
    return __fdividef(1.0f, 1.0f + __expf(-x));
}
__device__ __forceinline__ float tanh_acc(float x) {
    return 2.0f * sigf(2.0f * x) - 1.0f;
}
// two act values -> packed bf16x2 hi and lo words
__device__ __forceinline__ void make_act_pair(float mu, float sg, float e0, float e1,
                                              uint32_t& hi, uint32_t& lo) {
    float a0 = fminf(fmaxf(fmaf(sg, e0, mu), 0.0f), 1.0f);
    float a1 = fminf(fmaxf(fmaf(sg, e1, mu), 0.0f), 1.0f);
    __nv_bfloat16 h0 = __float2bfloat16_rn(a0);
    __nv_bfloat16 h1 = __float2bfloat16_rn(a1);
    __nv_bfloat162 hp = __halves2bfloat162(h0, h1);
    hi = *reinterpret_cast<uint32_t*>(&hp);
    __nv_bfloat162 lp = __halves2bfloat162(
        __float2bfloat16_rn(a0 - __bfloat162float(h0)),
        __float2bfloat16_rn(a1 - __bfloat162float(h1)));
    lo = *reinterpret_cast<uint32_t*>(&lp);
}

// rkern (1024 x 4096) -> Bhi/Blo rows n' = 4j+q, k-major
__global__ __launch_bounds__(256) void convert_rkern_kernel(const float* __restrict__ rk) {
    __shared__ float tile[32][33];
    int n0 = blockIdx.x * 32, k0 = blockIdx.y * 32;
    int tid = threadIdx.x;
    for (int e = tid; e < 1024; e += 256) {
        int kr = e >> 5, nc = e & 31;
        tile[kr][nc] = rk[(size_t)(k0 + kr) * 4096 + n0 + nc];
    }
    __syncthreads();
    int nl = tid >> 3, ks = tid & 7;
    int n = n0 + nl;
    int q = n >> 10, j = n & 1023;
    int np = j * 4 + q;
    #pragma unroll
    for (int i = 0; i < 4; ++i) {
        int k = k0 + ks * 4 + i;
        float x = tile[ks * 4 + i][nl];
        __nv_bfloat16 hi = __float2bfloat16_rn(x);
        g_Bhi[(size_t)np * 1024 + k] = hi;
        g_Blo[(size_t)np * 1024 + k] = __float2bfloat16_rn(x - __bfloat162float(hi));
    }
}

// kern (64 x 4096) -> Khi/Klo rows n' = 4j+q, k-major (len 64)
__global__ __launch_bounds__(256) void convert_kern_kernel(const float* __restrict__ kn) {
    __shared__ float tile[32][33];
    int n0 = blockIdx.x * 32, k0 = blockIdx.y * 32;
    int tid = threadIdx.x;
    for (int e = tid; e < 1024; e += 256) {
        int kr = e >> 5, nc = e & 31;
        tile[kr][nc] = kn[(size_t)(k0 + kr) * 4096 + n0 + nc];
    }
    __syncthreads();
    int nl = tid >> 3, ks = tid & 7;
    int n = n0 + nl;
    int q = n >> 10, j = n & 1023;
    int np = j * 4 + q;
    #pragma unroll
    for (int i = 0; i < 4; ++i) {
        int k = k0 + ks * 4 + i;
        float x = tile[ks * 4 + i][nl];
        __nv_bfloat16 hi = __float2bfloat16_rn(x);
        g_Khi[(size_t)np * 64 + k] = hi;
        g_Klo[(size_t)np * 64 + k] = __float2bfloat16_rn(x - __bfloat162float(hi));
    }
}

// ---------------- t=0 kernel: mu/sigma from context_state; zero-init h/c ----------------
__global__ __launch_bounds__(256) void act0_kernel(
    const float* __restrict__ cs,
    const float* __restrict__ w1, const float* __restrict__ b1,
    const float* __restrict__ w2, const float* __restrict__ b2,
    float* __restrict__ out)
{
    const int tid = threadIdx.x;
    const int wrow = tid >> 5;
    const int lane = tid & 31;
    const int row = blockIdx.x * 8 + wrow;
    const int k0 = lane * 32;

    // zero-init this block's 8 rows of h (buffer 0) and c
    {
        size_t base = (size_t)blockIdx.x * 8 * HH;
        for (int i = tid; i < 8 * HH / 2; i += 256) {
            ((uint32_t*)&g_hhi[0][base])[i] = 0u;
            ((uint32_t*)&g_hlo[0][base])[i] = 0u;
            ((float2*)&g_c[base])[i] = make_float2(0.0f, 0.0f);
        }
    }

    float s1 = 0.0f, s2 = 0.0f;
    const float* srow = cs + (size_t)row * (3 * HH) + 2 * HH + k0;
    #pragma unroll
    for (int i = 0; i < 8; ++i) {
        float4 v = *(const float4*)(srow + i * 4);
        const float* wp1 = w1 + k0 + i * 4;
        const float* wp2 = w2 + k0 + i * 4;
        s1 = fmaf(v.x, wp1[0], s1); s2 = fmaf(v.x, wp2[0], s2);
        s1 = fmaf(v.y, wp1[1], s1); s2 = fmaf(v.y, wp2[1], s2);
        s1 = fmaf(v.z, wp1[2], s1); s2 = fmaf(v.z, wp2[2], s2);
        s1 = fmaf(v.w, wp1[3], s1); s2 = fmaf(v.w, wp2[3], s2);
    }
    #pragma unroll
    for (int off = 16; off > 0; off >>= 1) {
        s1 += __shfl_xor_sync(0xffffffffu, s1, off);
        s2 += __shfl_xor_sync(0xffffffffu, s2, off);
    }
    if (lane == 0) {
        float mu = fmaxf(s1 + b1[0], 0.0f);
        float xr = fmaxf(s2 + b2[0], 0.0f);
        float sg = xr + log1pf(expf(-xr)) + 1e-8f;
        g_mu[row] = mu;
        g_sg[row] = sg;
        out[row] = mu;                       // mus t=0
        out[(size_t)TT * BB + row] = sg;     // sigmas t=0
    }
}

// ---------------- cp.async tile loaders ----------------
__device__ __forceinline__ void issue_tile_loads_AB(
    uint32_t sA, int tid, int mrow0, int ncol0,
    const __nv_bfloat16* ah, const __nv_bfloat16* al,
    const __nv_bfloat16* bh, const __nv_bfloat16* bl, int koff)
{
    const int lrow = tid >> 2, lch = tid & 3;
    #pragma unroll
    for (int rr = 0; rr < 2; ++rr) {
        int m = lrow + rr * 64;
        uint32_t d = sA + (uint32_t)(m * 64 + ((lch ^ ((m >> 1) & 3)) << 4));
        size_t gsrc = (size_t)(mrow0 + m) * 1024 + koff + lch * 8;
        cpa16(d + OFF_AHI, ah + gsrc);
        cpa16(d + OFF_ALO, al + gsrc);
    }
    #pragma unroll
    for (int rr = 0; rr < 2; ++rr) {
        int n = lrow + rr * 64;
        uint32_t d = sA + (uint32_t)(n * 64 + ((lch ^ ((n >> 1) & 3)) << 4));
        size_t gsrc = (size_t)(ncol0 + n) * 1024 + koff + lch * 8;
        cpa16(d + OFF_BHI, bh + gsrc);
        cpa16(d + OFF_BLO, bl + gsrc);
    }
}
__device__ __forceinline__ void issue_tile_loads_Bonly(
    uint32_t sA, int tid, int ncol0,
    const __nv_bfloat16* bh, const __nv_bfloat16* bl, int koff)
{
    const int lrow = tid >> 2, lch = tid & 3;
    #pragma unroll
    for (int rr = 0; rr < 2; ++rr) {
        int n = lrow + rr * 64;
        uint32_t d = sA + (uint32_t)(n * 64 + ((lch ^ ((n >> 1) & 3)) << 4));
        size_t gsrc = (size_t)(ncol0 + n) * 64 + koff + lch * 8;
        cpa16(d + OFF_BHI, bh + gsrc);
        cpa16(d + OFF_BLO, bl + gsrc);
    }
}

// ---------------- main fused GEMM + act + gate kernel ----------------
__global__ __launch_bounds__(NTH, 2) void gemm_step_kernel(
    const float* __restrict__ bias,
    const float* __restrict__ w1, const float* __restrict__ w2,
    const float* __restrict__ b1, const float* __restrict__ b2,
    const float* __restrict__ eps_t,
    float* __restrict__ out, int t, int hb)
{
    extern __shared__ char smem[];
    __shared__ float sbias[4][32];
    __shared__ float w1s[32], w2s[32];
    __shared__ float mu_s[128], sg_s[128];
    __shared__ float red_s[2][4][128];
    const int tid = threadIdx.x;
    const int nblk = blockIdx.x;         // 0..31
    const int mblk = blockIdx.y;         // 0..7
    const int mrow0 = mblk * BM;
    const int ncol0 = nblk * BN;         // permuted n' space
    const uint32_t sbase = smem_u32(smem);

    const int lane = tid & 31;
    const int w = tid >> 5;
    const int wm = w >> 2;   // 0..1  (64 rows each)
    const int wn = w & 3;    // 0..3  (32 n' each)

    const __nv_bfloat16* hh_src = g_hhi[hb];
    const __nv_bfloat16* hl_src = g_hlo[hb];

    // ---- pipeline prologue: get loads in flight first ----
    issue_tile_loads_AB(sbase, tid, mrow0, ncol0, hh_src, hl_src, g_Bhi, g_Blo, 0);
    cp_commit();
    issue_tile_loads_AB(sbase + STAGE_BYTES, tid, mrow0, ncol0, hh_src, hl_src, g_Bhi, g_Blo, 32);
    cp_commit();

    // ---- small smem loads ----
    if (tid < 128) {
        sbias[tid >> 5][tid & 31] = bias[(size_t)(tid >> 5) * 1024 + nblk * 32 + (tid & 31)];
    } else if (tid < 160) {
        w1s[tid - 128] = w1[nblk * 32 + (tid - 128)];
    } else if (tid < 192) {
        w2s[tid - 160] = w2[nblk * 32 + (tid - 160)];
    }

    // ---- mu/sigma for this CTA's 128 rows ----
    if (t == 0) {
        if (tid < 128) mu_s[tid] = g_mu[mrow0 + tid];
        else sg_s[tid - 128] = g_sg[mrow0 + tid - 128];
    } else {
        if (tid < 128) {
            const float4* p = (const float4*)&g_p1[t & 1][(size_t)(mrow0 + tid) * 32];
            float a0 = 0, a1 = 0;
            #pragma unroll
            for (int i = 0; i < 4; ++i) {
                float4 v0 = p[i * 2], v1 = p[i * 2 + 1];
                a0 += (v0.x + v0.y) + (v0.z + v0.w);
                a1 += (v1.x + v1.y) + (v1.z + v1.w);
            }
            mu_s[tid] = a0 + a1;
        } else {
            const float4* p = (const float4*)&g_p2[t & 1][(size_t)(mrow0 + tid - 128) * 32];
            float a0 = 0, a1 = 0;
            #pragma unroll
            for (int i = 0; i < 4; ++i) {
                float4 v0 = p[i * 2], v1 = p[i * 2 + 1];
                a0 += (v0.x + v0.y) + (v0.z + v0.w);
                a1 += (v1.x + v1.y) + (v1.z + v1.w);
            }
            sg_s[tid - 128] = a0 + a1;
        }
    }
    __syncthreads();
    if (t != 0 && tid < 128) {
        float mu = fmaxf(mu_s[tid] + b1[0], 0.0f);
        float xr = fmaxf(sg_s[tid] + b2[0], 0.0f);
        float sg = xr + log1pf(expf(-xr)) + 1e-8f;
        mu_s[tid] = mu;
        sg_s[tid] = sg;
        if (nblk == 0) {
            out[(size_t)t * BB + mrow0 + tid] = mu;
            out[(size_t)TT * BB + (size_t)t * BB + mrow0 + tid] = sg;
        }
    }
    __syncthreads();

    // acts output (nblk==0 only)
    if (nblk == 0) {
        #pragma unroll 4
        for (int it = 0; it < 32; ++it) {
            int idx = tid + it * 256;
            int r = idx >> 6, f = idx & 63;
            float a = fminf(fmaxf(fmaf(sg_s[r], eps_t[(size_t)(mrow0 + r) * 64 + f], mu_s[r]), 0.0f), 1.0f);
            out[2 * (size_t)TT * BB + ((size_t)(mrow0 + r) * TT + t) * 64 + f] = a;
        }
    }

    // ---- fragment address precompute ----
    const int mat = lane >> 3;
    const int r8 = lane & 7;
    int a_off[4], a_sw[4];
    #pragma unroll
    for (int mt = 0; mt < 4; ++mt) {
        int m = wm * 64 + mt * 16 + r8 + (mat & 1) * 8;
        a_off[mt] = m * 64;
        a_sw[mt] = (m >> 1) & 3;
    }
    const int a_cbit = mat >> 1;
    int b_off[2], b_sw[2];
    #pragma unroll
    for (int np = 0; np < 2; ++np) {
        int n = wn * 32 + np * 16 + r8 + (mat >> 1) * 8;
        b_off[np] = n * 64;
        b_sw[np] = (n >> 1) & 3;
    }
    const int b_cbit = mat & 1;

    float acc[4][4][4];
    #pragma unroll
    for (int mt = 0; mt < 4; ++mt)
        #pragma unroll
        for (int nt = 0; nt < 4; ++nt)
            #pragma unroll
            for (int e = 0; e < 4; ++e)
                acc[mt][nt][e] = 0.0f;

    // ---- main loop (hot path identical to R8) ----
    for (int kt = 0; kt < KT_TOTAL; ++kt) {
        cp_wait1();
        __syncthreads();
        int kn = kt + 2;
        if (kn < 32) {
            uint32_t sN = sbase + (kn % NSTAGES) * STAGE_BYTES;
            issue_tile_loads_AB(sN, tid, mrow0, ncol0, hh_src, hl_src,
                                g_Bhi, g_Blo, kn * 32);
        } else if (kn < KT_TOTAL) {
            uint32_t sN = sbase + (kn % NSTAGES) * STAGE_BYTES;
            issue_tile_loads_Bonly(sN, tid, ncol0, g_Khi, g_Klo, (kn - 32) * 32);
            // stage act tile into A region (stage (kn%3) is free at this point)
            const int fbase = (kn - 32) * 32;
            const int m = tid >> 1;
            const int halfc = tid & 1;
            const float mu = mu_s[m];
            const float sg = sg_s[m];
            const float* ep = eps_t + (size_t)(mrow0 + m) * 64 + fbase;
            char* aregion = smem + (size_t)((kn % NSTAGES) * STAGE_BYTES);
            #pragma unroll
            for (int cc = 0; cc < 2; ++cc) {
                int lch = halfc * 2 + cc;
                float4 e0 = *(const float4*)(ep + lch * 8);
                float4 e1 = *(const float4*)(ep + lch * 8 + 4);
                uint4 hiv, lov;
                make_act_pair(mu, sg, e0.x, e0.y, hiv.x, lov.x);
                make_act_pair(mu, sg, e0.z, e0.w, hiv.y, lov.y);
                make_act_pair(mu, sg, e1.x, e1.y, hiv.z, lov.z);
                make_act_pair(mu, sg, e1.z, e1.w, hiv.w, lov.w);
                uint32_t o = (uint32_t)(m * 64 + ((lch ^ ((m >> 1) & 3)) << 4));
                *(uint4*)(aregion + OFF_AHI + o) = hiv;
                *(uint4*)(aregion + OFF_ALO + o) = lov;
            }
        }
        cp_commit();

        const uint32_t sA = sbase + (kt % NSTAGES) * STAGE_BYTES;
        #pragma unroll
        for (int s = 0; s < 2; ++s) {
            uint32_t ahi[4][4], bhi[2][4];
            #pragma unroll
            for (int mt = 0; mt < 4; ++mt)
                ldsm4(ahi[mt], sA + OFF_AHI + a_off[mt] + (((2 * s + a_cbit) ^ a_sw[mt]) << 4));
            #pragma unroll
            for (int np = 0; np < 2; ++np)
                ldsm4(bhi[np], sA + OFF_BHI + b_off[np] + (((2 * s + b_cbit) ^ b_sw[np]) << 4));
            // pass 1: hi*hi
            #pragma unroll
            for (int mt = 0; mt < 4; ++mt)
                #pragma unroll
                for (int nt = 0; nt < 4; ++nt)
                    mma_bf16(acc[mt][nt], ahi[mt], &bhi[nt >> 1][(nt & 1) * 2]);
            // pass 2: lo*hi
            {
                uint32_t alo[4][4];
                #pragma unroll
                for (int mt = 0; mt < 4; ++mt)
                    ldsm4(alo[mt], sA + OFF_ALO + a_off[mt] + (((2 * s + a_cbit) ^ a_sw[mt]) << 4));
                #pragma unroll
                for (int mt = 0; mt < 4; ++mt)
                    #pragma unroll
                    for (int nt = 0; nt < 4; ++nt)
                        mma_bf16(acc[mt][nt], alo[mt], &bhi[nt >> 1][(nt & 1) * 2]);
            }
            // pass 3: hi*lo
            {
                uint32_t blo[2][4];
                #pragma unroll
                for (int np = 0; np < 2; ++np)
                    ldsm4(blo[np], sA + OFF_BLO + b_off[np] + (((2 * s + b_cbit) ^ b_sw[np]) << 4));
                #pragma unroll
                for (int mt = 0; mt < 4; ++mt)
                    #pragma unroll
                    for (int nt = 0; nt < 4; ++nt)
                        mma_bf16(acc[mt][nt], ahi[mt], &blo[nt >> 1][(nt & 1) * 2]);
            }
        }
    }

    // ---- epilogue: gate exchange via shfl, LSTM update, mu/sigma partials ----
    const int odd = lane & 1;
    #pragma unroll
    for (int mt = 0; mt < 4; ++mt) {
        const int rl = wm * 64 + mt * 16 + (lane >> 2) + odd * 8;
        const int r = mrow0 + rl;
        float p1 = 0.0f, p2 = 0.0f;
        #pragma unroll
        for (int nt = 0; nt < 4; ++nt) {
            float* c = acc[mt][nt];
            float q0 = __shfl_xor_sync(0xffffffffu, c[0], 1);
            float q1 = __shfl_xor_sync(0xffffffffu, c[1], 1);
            float q2 = __shfl_xor_sync(0xffffffffu, c[2], 1);
            float q3 = __shfl_xor_sync(0xffffffffu, c[3], 1);
            float zi = odd ? q2 : c[0];
            float zf = odd ? q3 : c[1];
            float zg = odd ? c[2] : q0;
            float zo = odd ? c[3] : q1;
            int jl = wn * 8 + nt * 2 + ((lane & 3) >> 1);
            float vi = zi + sbias[0][jl];
            float vf = zf + sbias[1][jl];
            float vg = zg + sbias[2][jl];
            float vo = zo + sbias[3][jl];
            size_t idx = (size_t)r * 1024 + nblk * 32 + jl;
            float co = g_c[idx];
            float cn = sigf(vf) * co + sigf(vi) * tanh_acc(vg);
            float hn = sigf(vo) * tanh_acc(cn);
            g_c[idx] = cn;
            __nv_bfloat16 hh = __float2bfloat16_rn(hn);
            g_hhi[hb ^ 1][idx] = hh;
            g_hlo[hb ^ 1][idx] = __float2bfloat16_rn(hn - __bfloat162float(hh));
            p1 = fmaf(hn, w1s[jl], p1);
            p2 = fmaf(hn, w2s[jl], p2);
        }
        p1 += __shfl_xor_sync(0xffffffffu, p1, 2);
        p2 += __shfl_xor_sync(0xffffffffu, p2, 2);
        if ((lane & 2) == 0) {
            red_s[0][wn][rl] = p1;
            red_s[1][wn][rl] = p2;
        }
    }
    __syncthreads();
    // reduce across wn (fixed order, deterministic) -> one slot per (row, nblk)
    {
        int wb = (t + 1) & 1;
        if (tid < 128) {
            float v = (red_s[0][0][tid] + red_s[0][1][tid]) +
                      (red_s[0][2][tid] + red_s[0][3][tid]);
            g_p1[wb][(size_t)(mrow0 + tid) * 32 + nblk] = v;
        } else {
            int r2 = tid - 128;
            float v = (red_s[1][0][r2] + red_s[1][1][r2]) +
                      (red_s[1][2][r2] + red_s[1][3][r2]);
            g_p2[wb][(size_t)(mrow0 + r2) * 32 + nblk] = v;
        }
    }
}

// ---------------- host ----------------
extern "C" void kernel_launch(void* const* d_in, const int* in_sizes, int n_in,
                              void* d_out, int out_size) {
    const float* cs    = (const float*)d_in[0];
    const float* w1    = (const float*)d_in[1];
    const float* b1    = (const float*)d_in[2];
    const float* w2    = (const float*)d_in[3];
    const float* b2    = (const float*)d_in[4];
    const float* kern  = (const float*)d_in[5];
    const float* rkern = (const float*)d_in[6];
    const float* bias  = (const float*)d_in[7];
    const float* eps   = (const float*)d_in[8];
    float* out = (float*)d_out;

    cudaFuncSetAttribute(gemm_step_kernel,
                         cudaFuncAttributeMaxDynamicSharedMemorySize, SMEM_TOTAL);

    // launch order: conv, conv, act0, gemm t0 -> gemm lands in ncu slot 5
    convert_rkern_kernel<<<dim3(4096 / 32, 1024 / 32), 256>>>(rkern);
    convert_kern_kernel<<<dim3(4096 / 32, 64 / 32), 256>>>(kern);
    act0_kernel<<<128, 256>>>(cs, w1, b1, w2, b2, out);

    dim3 g2(32, 8);  // nblk x mblk = 256 CTAs (2 per SM)
    for (int t = 0; t < TT; ++t) {
        gemm_step_kernel<<<g2, NTH, SMEM_TOTAL>>>(
            bias, w1, w2, b1, b2, eps + (size_t)t * BB * FF, out, t, t & 1);
    }
}

// round 14
// speedup vs baseline: 1.4242x; 1.1414x over previous
#include <cuda_runtime.h>
#include <cuda_fp16.h>
#include <stdint.h>
#include <math.h>

// B,H,F,T = 1024,1024,64,48
#define BB 1024
#define HH 1024
#define FF 64
#define TT 48

#define BM 128
#define BN 128
#define NTH 256
#define KT_TOTAL 34   // 32 h-tiles + 2 act-tiles

// smem stage layout (bytes): A hi 8K, A lo 8K, B 8K (fp16, B single precision level)
#define OFF_AHI 0
#define OFF_ALO 8192
#define OFF_BHI 16384
#define STAGE_BYTES 24576
#define NSTAGES 4
#define SMEM_TOTAL (NSTAGES * STAGE_BYTES)

// ---------------- persistent device state ----------------
__device__ __half g_hhi[2][BB * HH];
__device__ __half g_hlo[2][BB * HH];
__device__ float  g_c[BB * HH];
__device__ __half g_Bh[4096 * 1024];   // permuted rkernel fp16, row n' = 4j+q, len 1024
__device__ __half g_Kh[4096 * 64];     // permuted kernel fp16, row n' = 4j+q, len 64
// per-(row,nblk) mu/sigma partials, double-buffered by step parity
__device__ float g_p1[2][BB * 32];
__device__ float g_p2[2][BB * 32];
// t=0 mu/sigma (from context_state)
__device__ float g_mu[BB];
__device__ float g_sg[BB];

// ---------------- helpers ----------------
__device__ __forceinline__ uint32_t smem_u32(const void* p) {
    uint32_t a;
    asm("{ .reg .u64 t; cvta.to.shared.u64 t, %1; cvt.u32.u64 %0, t; }" : "=r"(a) : "l"(p));
    return a;
}
__device__ __forceinline__ void cpa16(uint32_t dst, const void* src) {
    asm volatile("cp.async.cg.shared.global [%0], [%1], 16;" :: "r"(dst), "l"(src));
}
__device__ __forceinline__ void cp_commit() {
    asm volatile("cp.async.commit_group;" ::: "memory");
}
__device__ __forceinline__ void cp_wait2() {
    asm volatile("cp.async.wait_group 2;" ::: "memory");
}
__device__ __forceinline__ void ldsm4(uint32_t r[4], uint32_t addr) {
    asm volatile("ldmatrix.sync.aligned.m8n8.x4.shared.b16 {%0,%1,%2,%3}, [%4];"
                 : "=r"(r[0]), "=r"(r[1]), "=r"(r[2]), "=r"(r[3]) : "r"(addr));
}
__device__ __forceinline__ void mma_f16(float c[4], const uint32_t a[4], const uint32_t b[2]) {
    asm volatile(
        "mma.sync.aligned.m16n8k16.row.col.f32.f16.f16.f32 "
        "{%0,%1,%2,%3}, {%4,%5,%6,%7}, {%8,%9}, {%0,%1,%2,%3};"
        : "+f"(c[0]), "+f"(c[1]), "+f"(c[2]), "+f"(c[3])
        : "r"(a[0]), "r"(a[1]), "r"(a[2]), "r"(a[3]), "r"(b[0]), "r"(b[1]));
}
__device__ __forceinline__ float sigf(float x) {
    return __fdividef(1.0f, 1.0f + __expf(-x));
}
__device__ __forceinline__ float tanh_acc(float x) {
    return 2.0f * sigf(2.0f * x) - 1.0f;
}
// two act values -> packed fp16x2 hi and lo words
__device__ __forceinline__ void make_act_pair(float mu, float sg, float e0, float e1,
                                              uint32_t& hi, uint32_t& lo) {
    float a0 = fminf(fmaxf(fmaf(sg, e0, mu), 0.0f), 1.0f);
    float a1 = fminf(fmaxf(fmaf(sg, e1, mu), 0.0f), 1.0f);
    __half h0 = __float2half_rn(a0);
    __half h1 = __float2half_rn(a1);
    __half2 hp = __halves2half2(h0, h1);
    hi = *reinterpret_cast<uint32_t*>(&hp);
    __half2 lp = __halves2half2(
        __float2half_rn(a0 - __half2float(h0)),
        __float2half_rn(a1 - __half2float(h1)));
    lo = *reinterpret_cast<uint32_t*>(&lp);
}

// rkern (1024 x 4096) -> g_Bh rows n' = 4j+q, k-major, fp16
__global__ __launch_bounds__(256) void convert_rkern_kernel(const float* __restrict__ rk) {
    __shared__ float tile[32][33];
    int n0 = blockIdx.x * 32, k0 = blockIdx.y * 32;
    int tid = threadIdx.x;
    for (int e = tid; e < 1024; e += 256) {
        int kr = e >> 5, nc = e & 31;
        tile[kr][nc] = rk[(size_t)(k0 + kr) * 4096 + n0 + nc];
    }
    __syncthreads();
    int nl = tid >> 3, ks = tid & 7;
    int n = n0 + nl;
    int q = n >> 10, j = n & 1023;
    int np = j * 4 + q;
    #pragma unroll
    for (int i = 0; i < 4; ++i) {
        int k = k0 + ks * 4 + i;
        g_Bh[(size_t)np * 1024 + k] = __float2half_rn(tile[ks * 4 + i][nl]);
    }
}

// kern (64 x 4096) -> g_Kh rows n' = 4j+q, k-major (len 64), fp16
__global__ __launch_bounds__(256) void convert_kern_kernel(const float* __restrict__ kn) {
    __shared__ float tile[32][33];
    int n0 = blockIdx.x * 32, k0 = blockIdx.y * 32;
    int tid = threadIdx.x;
    for (int e = tid; e < 1024; e += 256) {
        int kr = e >> 5, nc = e & 31;
        tile[kr][nc] = kn[(size_t)(k0 + kr) * 4096 + n0 + nc];
    }
    __syncthreads();
    int nl = tid >> 3, ks = tid & 7;
    int n = n0 + nl;
    int q = n >> 10, j = n & 1023;
    int np = j * 4 + q;
    #pragma unroll
    for (int i = 0; i < 4; ++i) {
        int k = k0 + ks * 4 + i;
        g_Kh[(size_t)np * 64 + k] = __float2half_rn(tile[ks * 4 + i][nl]);
    }
}

// ---------------- t=0 kernel: mu/sigma from context_state; zero-init h/c ----------------
__global__ __launch_bounds__(256) void act0_kernel(
    const float* __restrict__ cs,
    const float* __restrict__ w1, const float* __restrict__ b1,
    const float* __restrict__ w2, const float* __restrict__ b2,
    float* __restrict__ out)
{
    const int tid = threadIdx.x;
    const int wrow = tid >> 5;
    const int lane = tid & 31;
    const int row = blockIdx.x * 8 + wrow;
    const int k0 = lane * 32;

    // zero-init this block's 8 rows of h (buffer 0) and c
    {
        size_t base = (size_t)blockIdx.x * 8 * HH;
        for (int i = tid; i < 8 * HH / 2; i += 256) {
            ((uint32_t*)&g_hhi[0][base])[i] = 0u;
            ((uint32_t*)&g_hlo[0][base])[i] = 0u;
            ((float2*)&g_c[base])[i] = make_float2(0.0f, 0.0f);
        }
    }

    float s1 = 0.0f, s2 = 0.0f;
    const float* srow = cs + (size_t)row * (3 * HH) + 2 * HH + k0;
    #pragma unroll
    for (int i = 0; i < 8; ++i) {
        float4 v = *(const float4*)(srow + i * 4);
        const float* wp1 = w1 + k0 + i * 4;
        const float* wp2 = w2 + k0 + i * 4;
        s1 = fmaf(v.x, wp1[0], s1); s2 = fmaf(v.x, wp2[0], s2);
        s1 = fmaf(v.y, wp1[1], s1); s2 = fmaf(v.y, wp2[1], s2);
        s1 = fmaf(v.z, wp1[2], s1); s2 = fmaf(v.z, wp2[2], s2);
        s1 = fmaf(v.w, wp1[3], s1); s2 = fmaf(v.w, wp2[3], s2);
    }
    #pragma unroll
    for (int off = 16; off > 0; off >>= 1) {
        s1 += __shfl_xor_sync(0xffffffffu, s1, off);
        s2 += __shfl_xor_sync(0xffffffffu, s2, off);
    }
    if (lane == 0) {
        float mu = fmaxf(s1 + b1[0], 0.0f);
        float xr = fmaxf(s2 + b2[0], 0.0f);
        float sg = xr + log1pf(expf(-xr)) + 1e-8f;
        g_mu[row] = mu;
        g_sg[row] = sg;
        out[row] = mu;                       // mus t=0
        out[(size_t)TT * BB + row] = sg;     // sigmas t=0
    }
}

// ---------------- cp.async tile loaders ----------------
__device__ __forceinline__ void issue_tile_loads_AB(
    uint32_t sA, int tid, int mrow0, int ncol0,
    const __half* ah, const __half* al, const __half* bh, int koff)
{
    const int lrow = tid >> 2, lch = tid & 3;
    #pragma unroll
    for (int rr = 0; rr < 2; ++rr) {
        int m = lrow + rr * 64;
        uint32_t d = sA + (uint32_t)(m * 64 + ((lch ^ ((m >> 1) & 3)) << 4));
        size_t gsrc = (size_t)(mrow0 + m) * 1024 + koff + lch * 8;
        cpa16(d + OFF_AHI, ah + gsrc);
        cpa16(d + OFF_ALO, al + gsrc);
    }
    #pragma unroll
    for (int rr = 0; rr < 2; ++rr) {
        int n = lrow + rr * 64;
        uint32_t d = sA + (uint32_t)(n * 64 + ((lch ^ ((n >> 1) & 3)) << 4));
        size_t gsrc = (size_t)(ncol0 + n) * 1024 + koff + lch * 8;
        cpa16(d + OFF_BHI, bh + gsrc);
    }
}
__device__ __forceinline__ void issue_tile_loads_Bonly(
    uint32_t sA, int tid, int ncol0, const __half* bh, int koff)
{
    const int lrow = tid >> 2, lch = tid & 3;
    #pragma unroll
    for (int rr = 0; rr < 2; ++rr) {
        int n = lrow + rr * 64;
        uint32_t d = sA + (uint32_t)(n * 64 + ((lch ^ ((n >> 1) & 3)) << 4));
        size_t gsrc = (size_t)(ncol0 + n) * 64 + koff + lch * 8;
        cpa16(d + OFF_BHI, bh + gsrc);
    }
}

// ---------------- main fused GEMM + act + gate kernel ----------------
__global__ __launch_bounds__(NTH, 2) void gemm_step_kernel(
    const float* __restrict__ bias,
    const float* __restrict__ w1, const float* __restrict__ w2,
    const float* __restrict__ b1, const float* __restrict__ b2,
    const float* __restrict__ eps_t,
    float* __restrict__ out, int t, int hb)
{
    extern __shared__ char smem[];
    __shared__ float sbias[4][32];
    __shared__ float w1s[32], w2s[32];
    __shared__ float mu_s[128], sg_s[128];
    __shared__ float red_s[2][4][128];
    const int tid = threadIdx.x;
    const int nblk = blockIdx.x;         // 0..31
    const int mblk = blockIdx.y;         // 0..7
    const int mrow0 = mblk * BM;
    const int ncol0 = nblk * BN;         // permuted n' space
    const uint32_t sbase = smem_u32(smem);

    const int lane = tid & 31;
    const int w = tid >> 5;
    const int wm = w >> 2;   // 0..1  (64 rows each)
    const int wn = w & 3;    // 0..3  (32 n' each)

    const __half* hh_src = g_hhi[hb];
    const __half* hl_src = g_hlo[hb];

    // ---- pipeline prologue: 3 stages in flight ----
    issue_tile_loads_AB(sbase, tid, mrow0, ncol0, hh_src, hl_src, g_Bh, 0);
    cp_commit();
    issue_tile_loads_AB(sbase + STAGE_BYTES, tid, mrow0, ncol0, hh_src, hl_src, g_Bh, 32);
    cp_commit();
    issue_tile_loads_AB(sbase + 2 * STAGE_BYTES, tid, mrow0, ncol0, hh_src, hl_src, g_Bh, 64);
    cp_commit();

    // ---- small smem loads ----
    if (tid < 128) {
        sbias[tid >> 5][tid & 31] = bias[(size_t)(tid >> 5) * 1024 + nblk * 32 + (tid & 31)];
    } else if (tid < 160) {
        w1s[tid - 128] = w1[nblk * 32 + (tid - 128)];
    } else if (tid < 192) {
        w2s[tid - 160] = w2[nblk * 32 + (tid - 160)];
    }

    // ---- mu/sigma for this CTA's 128 rows ----
    if (t == 0) {
        if (tid < 128) mu_s[tid] = g_mu[mrow0 + tid];
        else sg_s[tid - 128] = g_sg[mrow0 + tid - 128];
    } else {
        if (tid < 128) {
            const float4* p = (const float4*)&g_p1[t & 1][(size_t)(mrow0 + tid) * 32];
            float a0 = 0, a1 = 0;
            #pragma unroll
            for (int i = 0; i < 4; ++i) {
                float4 v0 = p[i * 2], v1 = p[i * 2 + 1];
                a0 += (v0.x + v0.y) + (v0.z + v0.w);
                a1 += (v1.x + v1.y) + (v1.z + v1.w);
            }
            mu_s[tid] = a0 + a1;
        } else {
            const float4* p = (const float4*)&g_p2[t & 1][(size_t)(mrow0 + tid - 128) * 32];
            float a0 = 0, a1 = 0;
            #pragma unroll
            for (int i = 0; i < 4; ++i) {
                float4 v0 = p[i * 2], v1 = p[i * 2 + 1];
                a0 += (v0.x + v0.y) + (v0.z + v0.w);
                a1 += (v1.x + v1.y) + (v1.z + v1.w);
            }
            sg_s[tid - 128] = a0 + a1;
        }
    }
    __syncthreads();
    if (t != 0 && tid < 128) {
        float mu = fmaxf(mu_s[tid] + b1[0], 0.0f);
        float xr = fmaxf(sg_s[tid] + b2[0], 0.0f);
        float sg = xr + log1pf(expf(-xr)) + 1e-8f;
        mu_s[tid] = mu;
        sg_s[tid] = sg;
        if (nblk == 0) {
            out[(size_t)t * BB + mrow0 + tid] = mu;
            out[(size_t)TT * BB + (size_t)t * BB + mrow0 + tid] = sg;
        }
    }
    __syncthreads();

    // acts output (nblk==0 only)
    if (nblk == 0) {
        #pragma unroll 4
        for (int it = 0; it < 32; ++it) {
            int idx = tid + it * 256;
            int r = idx >> 6, f = idx & 63;
            float a = fminf(fmaxf(fmaf(sg_s[r], eps_t[(size_t)(mrow0 + r) * 64 + f], mu_s[r]), 0.0f), 1.0f);
            out[2 * (size_t)TT * BB + ((size_t)(mrow0 + r) * TT + t) * 64 + f] = a;
        }
    }

    // ---- fragment address precompute ----
    const int mat = lane >> 3;
    const int r8 = lane & 7;
    int a_off[4], a_sw[4];
    #pragma unroll
    for (int mt = 0; mt < 4; ++mt) {
        int m = wm * 64 + mt * 16 + r8 + (mat & 1) * 8;
        a_off[mt] = m * 64;
        a_sw[mt] = (m >> 1) & 3;
    }
    const int a_cbit = mat >> 1;
    int b_off[2], b_sw[2];
    #pragma unroll
    for (int np = 0; np < 2; ++np) {
        int n = wn * 32 + np * 16 + r8 + (mat >> 1) * 8;
        b_off[np] = n * 64;
        b_sw[np] = (n >> 1) & 3;
    }
    const int b_cbit = mat & 1;

    float acc[4][4][4];
    #pragma unroll
    for (int mt = 0; mt < 4; ++mt)
        #pragma unroll
        for (int nt = 0; nt < 4; ++nt)
            #pragma unroll
            for (int e = 0; e < 4; ++e)
                acc[mt][nt][e] = 0.0f;

    // ---- main loop ----
    for (int kt = 0; kt < KT_TOTAL; ++kt) {
        cp_wait2();
        __syncthreads();
        int kn = kt + 3;
        if (kn < 32) {
            uint32_t sN = sbase + (kn % NSTAGES) * STAGE_BYTES;
            issue_tile_loads_AB(sN, tid, mrow0, ncol0, hh_src, hl_src, g_Bh, kn * 32);
        } else if (kn < KT_TOTAL) {
            uint32_t sN = sbase + (kn % NSTAGES) * STAGE_BYTES;
            issue_tile_loads_Bonly(sN, tid, ncol0, g_Kh, (kn - 32) * 32);
            // stage act tile into A region (stage (kn%4) is free at this point)
            const int fbase = (kn - 32) * 32;
            const int m = tid >> 1;
            const int halfc = tid & 1;
            const float mu = mu_s[m];
            const float sg = sg_s[m];
            const float* ep = eps_t + (size_t)(mrow0 + m) * 64 + fbase;
            char* aregion = smem + (size_t)((kn % NSTAGES) * STAGE_BYTES);
            #pragma unroll
            for (int cc = 0; cc < 2; ++cc) {
                int lch = halfc * 2 + cc;
                float4 e0 = *(const float4*)(ep + lch * 8);
                float4 e1 = *(const float4*)(ep + lch * 8 + 4);
                uint4 hiv, lov;
                make_act_pair(mu, sg, e0.x, e0.y, hiv.x, lov.x);
                make_act_pair(mu, sg, e0.z, e0.w, hiv.y, lov.y);
                make_act_pair(mu, sg, e1.x, e1.y, hiv.z, lov.z);
                make_act_pair(mu, sg, e1.z, e1.w, hiv.w, lov.w);
                uint32_t o = (uint32_t)(m * 64 + ((lch ^ ((m >> 1) & 3)) << 4));
                *(uint4*)(aregion + OFF_AHI + o) = hiv;
                *(uint4*)(aregion + OFF_ALO + o) = lov;
            }
        }
        cp_commit();

        const uint32_t sA = sbase + (kt % NSTAGES) * STAGE_BYTES;
        #pragma unroll
        for (int s = 0; s < 2; ++s) {
            uint32_t ahi[4][4], bhi[2][4];
            #pragma unroll
            for (int mt = 0; mt < 4; ++mt)
                ldsm4(ahi[mt], sA + OFF_AHI + a_off[mt] + (((2 * s + a_cbit) ^ a_sw[mt]) << 4));
            #pragma unroll
            for (int np = 0; np < 2; ++np)
                ldsm4(bhi[np], sA + OFF_BHI + b_off[np] + (((2 * s + b_cbit) ^ b_sw[np]) << 4));
            // pass 1: ahi * b
            #pragma unroll
            for (int mt = 0; mt < 4; ++mt)
                #pragma unroll
                for (int nt = 0; nt < 4; ++nt)
                    mma_f16(acc[mt][nt], ahi[mt], &bhi[nt >> 1][(nt & 1) * 2]);
            // pass 2: alo * b
            {
                uint32_t alo[4][4];
                #pragma unroll
                for (int mt = 0; mt < 4; ++mt)
                    ldsm4(alo[mt], sA + OFF_ALO + a_off[mt] + (((2 * s + a_cbit) ^ a_sw[mt]) << 4));
                #pragma unroll
                for (int mt = 0; mt < 4; ++mt)
                    #pragma unroll
                    for (int nt = 0; nt < 4; ++nt)
                        mma_f16(acc[mt][nt], alo[mt], &bhi[nt >> 1][(nt & 1) * 2]);
            }
        }
    }

    // ---- epilogue: gate exchange via shfl, LSTM update, mu/sigma partials ----
    const int odd = lane & 1;
    #pragma unroll
    for (int mt = 0; mt < 4; ++mt) {
        const int rl = wm * 64 + mt * 16 + (lane >> 2) + odd * 8;
        const int r = mrow0 + rl;
        float p1 = 0.0f, p2 = 0.0f;
        #pragma unroll
        for (int nt = 0; nt < 4; ++nt) {
            float* c = acc[mt][nt];
            float q0 = __shfl_xor_sync(0xffffffffu, c[0], 1);
            float q1 = __shfl_xor_sync(0xffffffffu, c[1], 1);
            float q2 = __shfl_xor_sync(0xffffffffu, c[2], 1);
            float q3 = __shfl_xor_sync(0xffffffffu, c[3], 1);
            float zi = odd ? q2 : c[0];
            float zf = odd ? q3 : c[1];
            float zg = odd ? c[2] : q0;
            float zo = odd ? c[3] : q1;
            int jl = wn * 8 + nt * 2 + ((lane & 3) >> 1);
            float vi = zi + sbias[0][jl];
            float vf = zf + sbias[1][jl];
            float vg = zg + sbias[2][jl];
            float vo = zo + sbias[3][jl];
            size_t idx = (size_t)r * 1024 + nblk * 32 + jl;
            float co = g_c[idx];
            float cn = sigf(vf) * co + sigf(vi) * tanh_acc(vg);
            float hn = sigf(vo) * tanh_acc(cn);
            g_c[idx] = cn;
            __half hh = __float2half_rn(hn);
            g_hhi[hb ^ 1][idx] = hh;
            g_hlo[hb ^ 1][idx] = __float2half_rn(hn - __half2float(hh));
            p1 = fmaf(hn, w1s[jl], p1);
            p2 = fmaf(hn, w2s[jl], p2);
        }
        p1 += __shfl_xor_sync(0xffffffffu, p1, 2);
        p2 += __shfl_xor_sync(0xffffffffu, p2, 2);
        if ((lane & 2) == 0) {
            red_s[0][wn][rl] = p1;
            red_s[1][wn][rl] = p2;
        }
    }
    __syncthreads();
    // reduce across wn (fixed order, deterministic) -> one slot per (row, nblk)
    {
        int wb = (t + 1) & 1;
        if (tid < 128) {
            float v = (red_s[0][0][tid] + red_s[0][1][tid]) +
                      (red_s[0][2][tid] + red_s[0][3][tid]);
            g_p1[wb][(size_t)(mrow0 + tid) * 32 + nblk] = v;
        } else {
            int r2 = tid - 128;
            float v = (red_s[1][0][r2] + red_s[1][1][r2]) +
                      (red_s[1][2][r2] + red_s[1][3][r2]);
            g_p2[wb][(size_t)(mrow0 + r2) * 32 + nblk] = v;
        }
    }
}

// ---------------- host ----------------
extern "C" void kernel_launch(void* const* d_in, const int* in_sizes, int n_in,
                              void* d_out, int out_size) {
    const float* cs    = (const float*)d_in[0];
    const float* w1    = (const float*)d_in[1];
    const float* b1    = (const float*)d_in[2];
    const float* w2    = (const float*)d_in[3];
    const float* b2    = (const float*)d_in[4];
    const float* kern  = (const float*)d_in[5];
    const float* rkern = (const float*)d_in[6];
    const float* bias  = (const float*)d_in[7];
    const float* eps   = (const float*)d_in[8];
    float* out = (float*)d_out;

    cudaFuncSetAttribute(gemm_step_kernel,
                         cudaFuncAttributeMaxDynamicSharedMemorySize, SMEM_TOTAL);

    // launch order: conv, conv, act0, gemm t0 -> gemm lands in ncu slot 5
    convert_rkern_kernel<<<dim3(4096 / 32, 1024 / 32), 256>>>(rkern);
    convert_kern_kernel<<<dim3(4096 / 32, 64 / 32), 256>>>(kern);
    act0_kernel<<<128, 256>>>(cs, w1, b1, w2, b2, out);

    dim3 g2(32, 8);  // nblk x mblk = 256 CTAs (2 per SM)
    for (int t = 0; t < TT; ++t) {
        gemm_step_kernel<<<g2, NTH, SMEM_TOTAL>>>(
            bias, w1, w2, b1, b2, eps + (size_t)t * BB * FF, out, t, t & 1);
    }
}

// round 15
// speedup vs baseline: 1.7727x; 1.2448x over previous
#include <cuda_runtime.h>
#include <cuda_fp16.h>
#include <stdint.h>
#include <math.h>

// B,H,F,T = 1024,1024,64,48
#define BB 1024
#define HH 1024
#define FF 64
#define TT 48

#define BM 128
#define BN 128
#define NTH 256
#define KT_TOTAL 34   // 32 h-tiles + 2 act-tiles

// smem stage layout (bytes): A 8K, B 8K (both plain fp16)
#define OFF_A 0
#define OFF_B 8192
#define STAGE_BYTES 16384
#define NSTAGES 6
#define SMEM_TOTAL (NSTAGES * STAGE_BYTES)

// ---------------- persistent device state ----------------
__device__ __half g_h[2][BB * HH];
__device__ float  g_c[BB * HH];
__device__ __half g_Bh[4096 * 1024];   // permuted rkernel fp16, row n' = 4j+q, len 1024
__device__ __half g_Kh[4096 * 64];     // permuted kernel fp16, row n' = 4j+q, len 64
// per-(row,nblk) mu/sigma partials, double-buffered by step parity
__device__ float g_p1[2][BB * 32];
__device__ float g_p2[2][BB * 32];
// t=0 mu/sigma (from context_state)
__device__ float g_mu[BB];
__device__ float g_sg[BB];

// ---------------- helpers ----------------
__device__ __forceinline__ uint32_t smem_u32(const void* p) {
    uint32_t a;
    asm("{ .reg .u64 t; cvta.to.shared.u64 t, %1; cvt.u32.u64 %0, t; }" : "=r"(a) : "l"(p));
    return a;
}
__device__ __forceinline__ void cpa16(uint32_t dst, const void* src) {
    asm volatile("cp.async.cg.shared.global [%0], [%1], 16;" :: "r"(dst), "l"(src));
}
__device__ __forceinline__ void cp_commit() {
    asm volatile("cp.async.commit_group;" ::: "memory");
}
__device__ __forceinline__ void cp_wait1() {
    asm volatile("cp.async.wait_group 1;" ::: "memory");
}
__device__ __forceinline__ void ldsm4(uint32_t r[4], uint32_t addr) {
    asm volatile("ldmatrix.sync.aligned.m8n8.x4.shared.b16 {%0,%1,%2,%3}, [%4];"
                 : "=r"(r[0]), "=r"(r[1]), "=r"(r[2]), "=r"(r[3]) : "r"(addr));
}
__device__ __forceinline__ void mma_f16(float c[4], const uint32_t a[4], const uint32_t b[2]) {
    asm volatile(
        "mma.sync.aligned.m16n8k16.row.col.f32.f16.f16.f32 "
        "{%0,%1,%2,%3}, {%4,%5,%6,%7}, {%8,%9}, {%0,%1,%2,%3};"
        : "+f"(c[0]), "+f"(c[1]), "+f"(c[2]), "+f"(c[3])
        : "r"(a[0]), "r"(a[1]), "r"(a[2]), "r"(a[3]), "r"(b[0]), "r"(b[1]));
}
__device__ __forceinline__ float sigf(float x) {
    return __fdividef(1.0f, 1.0f + __expf(-x));
}
__device__ __forceinline__ float tanh_acc(float x) {
    return 2.0f * sigf(2.0f * x) - 1.0f;
}
// two act values -> packed fp16x2 word
__device__ __forceinline__ uint32_t make_act_pair(float mu, float sg, float e0, float e1) {
    float a0 = fminf(fmaxf(fmaf(sg, e0, mu), 0.0f), 1.0f);
    float a1 = fminf(fmaxf(fmaf(sg, e1, mu), 0.0f), 1.0f);
    __half2 hp = __halves2half2(__float2half_rn(a0), __float2half_rn(a1));
    return *reinterpret_cast<uint32_t*>(&hp);
}

// rkern (1024 x 4096) -> g_Bh rows n' = 4j+q, k-major, fp16
__global__ __launch_bounds__(256) void convert_rkern_kernel(const float* __restrict__ rk) {
    __shared__ float tile[32][33];
    int n0 = blockIdx.x * 32, k0 = blockIdx.y * 32;
    int tid = threadIdx.x;
    for (int e = tid; e < 1024; e += 256) {
        int kr = e >> 5, nc = e & 31;
        tile[kr][nc] = rk[(size_t)(k0 + kr) * 4096 + n0 + nc];
    }
    __syncthreads();
    int nl = tid >> 3, ks = tid & 7;
    int n = n0 + nl;
    int q = n >> 10, j = n & 1023;
    int np = j * 4 + q;
    #pragma unroll
    for (int i = 0; i < 4; ++i) {
        int k = k0 + ks * 4 + i;
        g_Bh[(size_t)np * 1024 + k] = __float2half_rn(tile[ks * 4 + i][nl]);
    }
}

// kern (64 x 4096) -> g_Kh rows n' = 4j+q, k-major (len 64), fp16
__global__ __launch_bounds__(256) void convert_kern_kernel(const float* __restrict__ kn) {
    __shared__ float tile[32][33];
    int n0 = blockIdx.x * 32, k0 = blockIdx.y * 32;
    int tid = threadIdx.x;
    for (int e = tid; e < 1024; e += 256) {
        int kr = e >> 5, nc = e & 31;
        tile[kr][nc] = kn[(size_t)(k0 + kr) * 4096 + n0 + nc];
    }
    __syncthreads();
    int nl = tid >> 3, ks = tid & 7;
    int n = n0 + nl;
    int q = n >> 10, j = n & 1023;
    int np = j * 4 + q;
    #pragma unroll
    for (int i = 0; i < 4; ++i) {
        int k = k0 + ks * 4 + i;
        g_Kh[(size_t)np * 64 + k] = __float2half_rn(tile[ks * 4 + i][nl]);
    }
}

// ---------------- t=0 kernel: mu/sigma from context_state; zero-init h/c ----------------
__global__ __launch_bounds__(256) void act0_kernel(
    const float* __restrict__ cs,
    const float* __restrict__ w1, const float* __restrict__ b1,
    const float* __restrict__ w2, const float* __restrict__ b2,
    float* __restrict__ out)
{
    const int tid = threadIdx.x;
    const int wrow = tid >> 5;
    const int lane = tid & 31;
    const int row = blockIdx.x * 8 + wrow;
    const int k0 = lane * 32;

    // zero-init this block's 8 rows of h (buffer 0) and c
    {
        size_t base = (size_t)blockIdx.x * 8 * HH;
        for (int i = tid; i < 8 * HH / 2; i += 256) {
            ((uint32_t*)&g_h[0][base])[i] = 0u;
            ((float2*)&g_c[base])[i] = make_float2(0.0f, 0.0f);
        }
    }

    float s1 = 0.0f, s2 = 0.0f;
    const float* srow = cs + (size_t)row * (3 * HH) + 2 * HH + k0;
    #pragma unroll
    for (int i = 0; i < 8; ++i) {
        float4 v = *(const float4*)(srow + i * 4);
        const float* wp1 = w1 + k0 + i * 4;
        const float* wp2 = w2 + k0 + i * 4;
        s1 = fmaf(v.x, wp1[0], s1); s2 = fmaf(v.x, wp2[0], s2);
        s1 = fmaf(v.y, wp1[1], s1); s2 = fmaf(v.y, wp2[1], s2);
        s1 = fmaf(v.z, wp1[2], s1); s2 = fmaf(v.z, wp2[2], s2);
        s1 = fmaf(v.w, wp1[3], s1); s2 = fmaf(v.w, wp2[3], s2);
    }
    #pragma unroll
    for (int off = 16; off > 0; off >>= 1) {
        s1 += __shfl_xor_sync(0xffffffffu, s1, off);
        s2 += __shfl_xor_sync(0xffffffffu, s2, off);
    }
    if (lane == 0) {
        float mu = fmaxf(s1 + b1[0], 0.0f);
        float xr = fmaxf(s2 + b2[0], 0.0f);
        float sg = xr + log1pf(expf(-xr)) + 1e-8f;
        g_mu[row] = mu;
        g_sg[row] = sg;
        out[row] = mu;                       // mus t=0
        out[(size_t)TT * BB + row] = sg;     // sigmas t=0
    }
}

// ---------------- cp.async tile loaders ----------------
__device__ __forceinline__ void issue_tile_loads_AB(
    uint32_t sA, int tid, int mrow0, int ncol0,
    const __half* ah, const __half* bh, int koff)
{
    const int lrow = tid >> 2, lch = tid & 3;
    #pragma unroll
    for (int rr = 0; rr < 2; ++rr) {
        int m = lrow + rr * 64;
        uint32_t d = sA + (uint32_t)(m * 64 + ((lch ^ ((m >> 1) & 3)) << 4));
        size_t gsrc = (size_t)(mrow0 + m) * 1024 + koff + lch * 8;
        cpa16(d + OFF_A, ah + gsrc);
    }
    #pragma unroll
    for (int rr = 0; rr < 2; ++rr) {
        int n = lrow + rr * 64;
        uint32_t d = sA + (uint32_t)(n * 64 + ((lch ^ ((n >> 1) & 3)) << 4));
        size_t gsrc = (size_t)(ncol0 + n) * 1024 + koff + lch * 8;
        cpa16(d + OFF_B, bh + gsrc);
    }
}
__device__ __forceinline__ void issue_tile_loads_Bonly(
    uint32_t sA, int tid, int ncol0, const __half* bh, int koff)
{
    const int lrow = tid >> 2, lch = tid & 3;
    #pragma unroll
    for (int rr = 0; rr < 2; ++rr) {
        int n = lrow + rr * 64;
        uint32_t d = sA + (uint32_t)(n * 64 + ((lch ^ ((n >> 1) & 3)) << 4));
        size_t gsrc = (size_t)(ncol0 + n) * 64 + koff + lch * 8;
        cpa16(d + OFF_B, bh + gsrc);
    }
}

// ---------------- main fused GEMM + act + gate kernel ----------------
__global__ __launch_bounds__(NTH, 2) void gemm_step_kernel(
    const float* __restrict__ bias,
    const float* __restrict__ w1, const float* __restrict__ w2,
    const float* __restrict__ b1, const float* __restrict__ b2,
    const float* __restrict__ eps_t,
    float* __restrict__ out, int t, int hb)
{
    extern __shared__ char smem[];
    __shared__ float sbias[4][32];
    __shared__ float w1s[32], w2s[32];
    __shared__ float mu_s[128], sg_s[128];
    __shared__ float red_s[2][4][128];
    const int tid = threadIdx.x;
    const int nblk = blockIdx.x;         // 0..31
    const int mblk = blockIdx.y;         // 0..7
    const int mrow0 = mblk * BM;
    const int ncol0 = nblk * BN;         // permuted n' space
    const uint32_t sbase = smem_u32(smem);

    const int lane = tid & 31;
    const int w = tid >> 5;
    const int wm = w >> 2;   // 0..1  (64 rows each)
    const int wn = w & 3;    // 0..3  (32 n' each)

    const __half* h_src = g_h[hb];

    // ---- pipeline prologue: 2 groups of 2 kt ----
    issue_tile_loads_AB(sbase + 0 * STAGE_BYTES, tid, mrow0, ncol0, h_src, g_Bh, 0);
    issue_tile_loads_AB(sbase + 1 * STAGE_BYTES, tid, mrow0, ncol0, h_src, g_Bh, 32);
    cp_commit();
    issue_tile_loads_AB(sbase + 2 * STAGE_BYTES, tid, mrow0, ncol0, h_src, g_Bh, 64);
    issue_tile_loads_AB(sbase + 3 * STAGE_BYTES, tid, mrow0, ncol0, h_src, g_Bh, 96);
    cp_commit();

    // ---- small smem loads ----
    if (tid < 128) {
        sbias[tid >> 5][tid & 31] = bias[(size_t)(tid >> 5) * 1024 + nblk * 32 + (tid & 31)];
    } else if (tid < 160) {
        w1s[tid - 128] = w1[nblk * 32 + (tid - 128)];
    } else if (tid < 192) {
        w2s[tid - 160] = w2[nblk * 32 + (tid - 160)];
    }

    // ---- mu/sigma for this CTA's 128 rows ----
    if (t == 0) {
        if (tid < 128) mu_s[tid] = g_mu[mrow0 + tid];
        else sg_s[tid - 128] = g_sg[mrow0 + tid - 128];
    } else {
        if (tid < 128) {
            const float4* p = (const float4*)&g_p1[t & 1][(size_t)(mrow0 + tid) * 32];
            float a0 = 0, a1 = 0;
            #pragma unroll
            for (int i = 0; i < 4; ++i) {
                float4 v0 = p[i * 2], v1 = p[i * 2 + 1];
                a0 += (v0.x + v0.y) + (v0.z + v0.w);
                a1 += (v1.x + v1.y) + (v1.z + v1.w);
            }
            mu_s[tid] = a0 + a1;
        } else {
            const float4* p = (const float4*)&g_p2[t & 1][(size_t)(mrow0 + tid - 128) * 32];
            float a0 = 0, a1 = 0;
            #pragma unroll
            for (int i = 0; i < 4; ++i) {
                float4 v0 = p[i * 2], v1 = p[i * 2 + 1];
                a0 += (v0.x + v0.y) + (v0.z + v0.w);
                a1 += (v1.x + v1.y) + (v1.z + v1.w);
            }
            sg_s[tid - 128] = a0 + a1;
        }
    }
    __syncthreads();
    if (t != 0 && tid < 128) {
        float mu = fmaxf(mu_s[tid] + b1[0], 0.0f);
        float xr = fmaxf(sg_s[tid] + b2[0], 0.0f);
        float sg = xr + log1pf(expf(-xr)) + 1e-8f;
        mu_s[tid] = mu;
        sg_s[tid] = sg;
        if (nblk == 0) {
            out[(size_t)t * BB + mrow0 + tid] = mu;
            out[(size_t)TT * BB + (size_t)t * BB + mrow0 + tid] = sg;
        }
    }
    __syncthreads();

    // acts output (nblk==0 only)
    if (nblk == 0) {
        #pragma unroll 4
        for (int it = 0; it < 32; ++it) {
            int idx = tid + it * 256;
            int r = idx >> 6, f = idx & 63;
            float a = fminf(fmaxf(fmaf(sg_s[r], eps_t[(size_t)(mrow0 + r) * 64 + f], mu_s[r]), 0.0f), 1.0f);
            out[2 * (size_t)TT * BB + ((size_t)(mrow0 + r) * TT + t) * 64 + f] = a;
        }
    }

    // ---- fragment address precompute ----
    const int mat = lane >> 3;
    const int r8 = lane & 7;
    int a_off[4], a_sw[4];
    #pragma unroll
    for (int mt = 0; mt < 4; ++mt) {
        int m = wm * 64 + mt * 16 + r8 + (mat & 1) * 8;
        a_off[mt] = m * 64;
        a_sw[mt] = (m >> 1) & 3;
    }
    const int a_cbit = mat >> 1;
    int b_off[2], b_sw[2];
    #pragma unroll
    for (int np = 0; np < 2; ++np) {
        int n = wn * 32 + np * 16 + r8 + (mat >> 1) * 8;
        b_off[np] = n * 64;
        b_sw[np] = (n >> 1) & 3;
    }
    const int b_cbit = mat & 1;

    float acc[4][4][4];
    #pragma unroll
    for (int mt = 0; mt < 4; ++mt)
        #pragma unroll
        for (int nt = 0; nt < 4; ++nt)
            #pragma unroll
            for (int e = 0; e < 4; ++e)
                acc[mt][nt][e] = 0.0f;

    // ---- main loop: 17 iterations, 2 kt each ----
    for (int it = 0; it < KT_TOTAL / 2; ++it) {
        cp_wait1();
        __syncthreads();
        #pragma unroll
        for (int half = 0; half < 2; ++half) {
            int kj = 2 * it + 4 + half;
            if (kj < 32) {
                uint32_t sN = sbase + (kj % NSTAGES) * STAGE_BYTES;
                issue_tile_loads_AB(sN, tid, mrow0, ncol0, h_src, g_Bh, kj * 32);
            } else if (kj < KT_TOTAL) {
                uint32_t sN = sbase + (kj % NSTAGES) * STAGE_BYTES;
                issue_tile_loads_Bonly(sN, tid, ncol0, g_Kh, (kj - 32) * 32);
                // stage act tile into A region (stage free: consumed 2 iters ago)
                const int fbase = (kj - 32) * 32;
                const int m = tid >> 1;
                const int halfc = tid & 1;
                const float mu = mu_s[m];
                const float sg = sg_s[m];
                const float* ep = eps_t + (size_t)(mrow0 + m) * 64 + fbase;
                char* aregion = smem + (size_t)((kj % NSTAGES) * STAGE_BYTES);
                #pragma unroll
                for (int cc = 0; cc < 2; ++cc) {
                    int lch = halfc * 2 + cc;
                    float4 e0 = *(const float4*)(ep + lch * 8);
                    float4 e1 = *(const float4*)(ep + lch * 8 + 4);
                    uint4 hiv;
                    hiv.x = make_act_pair(mu, sg, e0.x, e0.y);
                    hiv.y = make_act_pair(mu, sg, e0.z, e0.w);
                    hiv.z = make_act_pair(mu, sg, e1.x, e1.y);
                    hiv.w = make_act_pair(mu, sg, e1.z, e1.w);
                    uint32_t o = (uint32_t)(m * 64 + ((lch ^ ((m >> 1) & 3)) << 4));
                    *(uint4*)(aregion + OFF_A + o) = hiv;
                }
            }
        }
        cp_commit();

        // compute both kt of this pair
        #pragma unroll
        for (int half = 0; half < 2; ++half) {
            const int kt = 2 * it + half;
            const uint32_t sA = sbase + (kt % NSTAGES) * STAGE_BYTES;
            #pragma unroll
            for (int s = 0; s < 2; ++s) {
                uint32_t av[4][4], bv[2][4];
                #pragma unroll
                for (int mt = 0; mt < 4; ++mt)
                    ldsm4(av[mt], sA + OFF_A + a_off[mt] + (((2 * s + a_cbit) ^ a_sw[mt]) << 4));
                #pragma unroll
                for (int np = 0; np < 2; ++np)
                    ldsm4(bv[np], sA + OFF_B + b_off[np] + (((2 * s + b_cbit) ^ b_sw[np]) << 4));
                #pragma unroll
                for (int mt = 0; mt < 4; ++mt)
                    #pragma unroll
                    for (int nt = 0; nt < 4; ++nt)
                        mma_f16(acc[mt][nt], av[mt], &bv[nt >> 1][(nt & 1) * 2]);
            }
        }
    }

    // ---- epilogue: gate exchange via shfl, LSTM update, mu/sigma partials ----
    const int odd = lane & 1;
    #pragma unroll
    for (int mt = 0; mt < 4; ++mt) {
        const int rl = wm * 64 + mt * 16 + (lane >> 2) + odd * 8;
        const int r = mrow0 + rl;
        float p1 = 0.0f, p2 = 0.0f;
        #pragma unroll
        for (int nt = 0; nt < 4; ++nt) {
            float* c = acc[mt][nt];
            float q0 = __shfl_xor_sync(0xffffffffu, c[0], 1);
            float q1 = __shfl_xor_sync(0xffffffffu, c[1], 1);
            float q2 = __shfl_xor_sync(0xffffffffu, c[2], 1);
            float q3 = __shfl_xor_sync(0xffffffffu, c[3], 1);
            float zi = odd ? q2 : c[0];
            float zf = odd ? q3 : c[1];
            float zg = odd ? c[2] : q0;
            float zo = odd ? c[3] : q1;
            int jl = wn * 8 + nt * 2 + ((lane & 3) >> 1);
            float vi = zi + sbias[0][jl];
            float vf = zf + sbias[1][jl];
            float vg = zg + sbias[2][jl];
            float vo = zo + sbias[3][jl];
            size_t idx = (size_t)r * 1024 + nblk * 32 + jl;
            float co = g_c[idx];
            float cn = sigf(vf) * co + sigf(vi) * tanh_acc(vg);
            float hn = sigf(vo) * tanh_acc(cn);
            g_c[idx] = cn;
            g_h[hb ^ 1][idx] = __float2half_rn(hn);
            p1 = fmaf(hn, w1s[jl], p1);
            p2 = fmaf(hn, w2s[jl], p2);
        }
        p1 += __shfl_xor_sync(0xffffffffu, p1, 2);
        p2 += __shfl_xor_sync(0xffffffffu, p2, 2);
        if ((lane & 2) == 0) {
            red_s[0][wn][rl] = p1;
            red_s[1][wn][rl] = p2;
        }
    }
    __syncthreads();
    // reduce across wn (fixed order, deterministic) -> one slot per (row, nblk)
    {
        int wb = (t + 1) & 1;
        if (tid < 128) {
            float v = (red_s[0][0][tid] + red_s[0][1][tid]) +
                      (red_s[0][2][tid] + red_s[0][3][tid]);
            g_p1[wb][(size_t)(mrow0 + tid) * 32 + nblk] = v;
        } else {
            int r2 = tid - 128;
            float v = (red_s[1][0][r2] + red_s[1][1][r2]) +
                      (red_s[1][2][r2] + red_s[1][3][r2]);
            g_p2[wb][(size_t)(mrow0 + r2) * 32 + nblk] = v;
        }
    }
}

// ---------------- host ----------------
extern "C" void kernel_launch(void* const* d_in, const int* in_sizes, int n_in,
                              void* d_out, int out_size) {
    const float* cs    = (const float*)d_in[0];
    const float* w1    = (const float*)d_in[1];
    const float* b1    = (const float*)d_in[2];
    const float* w2    = (const float*)d_in[3];
    const float* b2    = (const float*)d_in[4];
    const float* kern  = (const float*)d_in[5];
    const float* rkern = (const float*)d_in[6];
    const float* bias  = (const float*)d_in[7];
    const float* eps   = (const float*)d_in[8];
    float* out = (float*)d_out;

    cudaFuncSetAttribute(gemm_step_kernel,
                         cudaFuncAttributeMaxDynamicSharedMemorySize, SMEM_TOTAL);

    // launch order: conv, conv, act0, gemm t0 -> gemm lands in ncu slot 5
    convert_rkern_kernel<<<dim3(4096 / 32, 1024 / 32), 256>>>(rkern);
    convert_kern_kernel<<<dim3(4096 / 32, 64 / 32), 256>>>(kern);
    act0_kernel<<<128, 256>>>(cs, w1, b1, w2, b2, out);

    dim3 g2(32, 8);  // nblk x mblk = 256 CTAs (2 per SM)
    for (int t = 0; t < TT; ++t) {
        gemm_step_kernel<<<g2, NTH, SMEM_TOTAL>>>(
            bias, w1, w2, b1, b2, eps + (size_t)t * BB * FF, out, t, t & 1);
    }
}